// round 9
// baseline (speedup 1.0000x reference)
#include <cuda_runtime.h>
#include <math.h>

// SSMLayerFFTComplex: diagonal complex SSM (conjugate pairs) via exact linear
// recurrence instead of FFT convolution.
//
//   lam = -softplus(raw_lambda) + i*raw_omega          (per pair p)
//   A_d = exp(lam), factor = (A_d-1)/lam  (ZOH, DT=1)
//   w[b,p,t] = sum_i B_c[i,p] * u[b,i,t]               (real)
//   x[t]     = A_d * x[t-1] + factor * w[t]            (complex scan)
//   y[b,o,t] = sum_p C[p,o] * 2*Re(x[b,p,t])           (real GEMM)
//
// R8 post-mortem: FFMA2 cut instructions (issue 46->31%) but 62.5KB smem
// capped 3 blocks/SM -> 68-block tail wave ate the win. R9: keep FFMA2,
// shrink smem to 46KB via two-pass stage C (TS=32, single 17KB g buffer)
// -> 4 blocks/SM, all 512 blocks in ONE wave, occ 16->21%.

namespace {
constexpr int T_TOT  = 4096;
constexpr int IN_CH  = 32;
constexpr int OUT_CH = 32;
constexpr int NP     = 128;
constexpr int CHUNK  = 64;    // useful timesteps per block
constexpr int WARM   = 32;    // warm-up timesteps
constexpr int LW     = CHUNK + WARM;   // 96
constexpr int TS     = 32;             // timesteps per tile
constexpr int NTILE  = LW / TS;        // 3 (tile 0 = warm-up)
constexpr int US     = 96;             // u_s row stride
constexpr int GST    = 34;             // g row stride: even (b64-aligned), mod32=2 -> 2-way only

constexpr int U_FL = IN_CH * US;       // 3072
constexpr int C_FL = NP * OUT_CH;      // 4096
constexpr int G_FL = NP * GST;         // 4352
constexpr int SMEM_FLOATS = U_FL + C_FL + G_FL;        // 11520
constexpr int SMEM_BYTES  = SMEM_FLOATS * (int)sizeof(float);  // 46,080 B
}

typedef unsigned long long u64;

__device__ __forceinline__ u64 ffma2(u64 a, u64 b, u64 c) {
    u64 d;
    asm("fma.rn.f32x2 %0, %1, %2, %3;" : "=l"(d) : "l"(a), "l"(b), "l"(c));
    return d;
}
__device__ __forceinline__ u64 pack2(float lo, float hi) {
    u64 d;
    asm("mov.b64 %0, {%1, %2};" : "=l"(d) : "f"(lo), "f"(hi));
    return d;
}
__device__ __forceinline__ void unpack2(u64 v, float& lo, float& hi) {
    asm("mov.b64 {%0, %1}, %2;" : "=f"(lo), "=f"(hi) : "l"(v));
}

__global__ __launch_bounds__(128, 4)
void ssm_rec_kernel(const float* __restrict__ u,
                    const float* __restrict__ raw_lambda,
                    const float* __restrict__ raw_omega,
                    const float* __restrict__ Bc,   // [IN_CH][NP]
                    const float* __restrict__ Cp,   // [NP][OUT_CH]
                    float* __restrict__ y)          // [B][OUT_CH][T]
{
    extern __shared__ float smem[];
    float* u_s = smem;              // [IN_CH][US]
    float* C_s = u_s + U_FL;        // [NP][OUT_CH]
    float* g_s = C_s + C_FL;        // [NP][GST]  (one 32-t tile)

    const int tid   = threadIdx.x;
    const int wp    = tid >> 5;
    const int lane  = tid & 31;
    const int chunk = blockIdx.x;
    const int b     = blockIdx.y;
    const int t0    = chunk * CHUNK;

    const float* ug = u + (size_t)b * IN_CH * T_TOT;

    // ---- stage 0: cooperative loads ----
    for (int idx = tid; idx < IN_CH * LW; idx += 128) {
        int i  = idx / LW;
        int j  = idx - i * LW;
        int gt = t0 - WARM + j;
        u_s[i * US + j] = (gt >= 0) ? ug[i * T_TOT + gt] : 0.0f;
    }
    for (int idx = tid; idx < C_FL; idx += 128) C_s[idx] = Cp[idx];

    // ---- per-pair parameters (thread = pair p) ----
    const int p = tid;
    float rl = raw_lambda[p];
    float li = raw_omega[p];
    float lr = -log1pf(expf(rl));            // -softplus
    float er = expf(lr);
    float ar = er * cosf(li);                // A_d
    float ai = er * sinf(li);
    float nr = ar - 1.0f, ni = ai;
    float den = lr * lr + li * li;
    float fr, fi;
    if (den > 1e-12f) {
        float inv = 1.0f / den;
        fr = (nr * lr + ni * li) * inv;      // (A_d-1)/lam
        fi = (ni * lr - nr * li) * inv;
    } else {
        fr = 1.0f; fi = 0.0f;                // DT = 1
    }
    fr *= 2.0f; fi *= 2.0f;                  // fold 2*Re(conjugate pair)

    float bc[IN_CH];
#pragma unroll
    for (int i = 0; i < IN_CH; ++i) bc[i] = Bc[i * NP + p];

    // stage-C coordinates: thread = 8 channels x 1 timestep
    const int oct = lane & 3;                // channel octet 0..3
    const int tl  = wp * 8 + (lane >> 2);    // local t 0..31

    __syncthreads();

    float xr = 0.0f, xi = 0.0f;

    for (int tile = 0; tile < NTILE; ++tile) {
        const bool emit = (tile >= 1);

        // ---- stage A+B: packed input mix + scan, 8 timesteps per group ----
#pragma unroll 1
        for (int g8 = 0; g8 < TS; g8 += 8) {
            const int jb = tile * TS + g8;
            u64 w01 = 0ull, w23 = 0ull, w45 = 0ull, w67 = 0ull;
#pragma unroll
            for (int i = 0; i < IN_CH; ++i) {
                ulonglong2 ua = *reinterpret_cast<const ulonglong2*>(&u_s[i * US + jb]);
                ulonglong2 ub = *reinterpret_cast<const ulonglong2*>(&u_s[i * US + jb + 4]);
                u64 bb = pack2(bc[i], bc[i]);
                w01 = ffma2(bb, ua.x, w01);
                w23 = ffma2(bb, ua.y, w23);
                w45 = ffma2(bb, ub.x, w45);
                w67 = ffma2(bb, ub.y, w67);
            }
            float wv[8];
            unpack2(w01, wv[0], wv[1]);
            unpack2(w23, wv[2], wv[3]);
            unpack2(w45, wv[4], wv[5]);
            unpack2(w67, wv[6], wv[7]);

            float xrs[8];
#pragma unroll
            for (int k = 0; k < 8; ++k) {
                float nxr = fmaf(ar, xr, fmaf(-ai, xi, fr * wv[k]));
                float nxi = fmaf(ar, xi, fmaf( ai, xr, fi * wv[k]));
                xr = nxr; xi = nxi;
                xrs[k] = xr;                  // already x2 via factor
            }
            if (emit) {
                float* gr = &g_s[p * GST + g8];
                *reinterpret_cast<u64*>(gr + 0) = pack2(xrs[0], xrs[1]);
                *reinterpret_cast<u64*>(gr + 2) = pack2(xrs[2], xrs[3]);
                *reinterpret_cast<u64*>(gr + 4) = pack2(xrs[4], xrs[5]);
                *reinterpret_cast<u64*>(gr + 6) = pack2(xrs[6], xrs[7]);
            }
        }

        // ---- stage C: y[o, t] = sum_p C[p,o] * g[p,t] over the 32-t tile ----
        if (emit) {
            __syncthreads();   // g visible to all warps

            u64 a01 = 0ull, a23 = 0ull, a45 = 0ull, a67 = 0ull;
            const float* cb = C_s + oct * 8;
#pragma unroll 4
            for (int pp = 0; pp < NP; ++pp) {
                ulonglong2 cA = *reinterpret_cast<const ulonglong2*>(cb + pp * OUT_CH);
                ulonglong2 cB = *reinterpret_cast<const ulonglong2*>(cb + pp * OUT_CH + 4);
                float g = g_s[pp * GST + tl];
                u64 gg = pack2(g, g);
                a01 = ffma2(cA.x, gg, a01);
                a23 = ffma2(cA.y, gg, a23);
                a45 = ffma2(cB.x, gg, a45);
                a67 = ffma2(cB.y, gg, a67);
            }

            const int tg = t0 + (tile - 1) * TS + tl;
            float* yb = y + ((size_t)b * OUT_CH + oct * 8) * T_TOT + tg;
            float c0, c1;
            unpack2(a01, c0, c1);
            yb[0 * T_TOT] = c0;  yb[1 * T_TOT] = c1;
            unpack2(a23, c0, c1);
            yb[2 * T_TOT] = c0;  yb[3 * T_TOT] = c1;
            unpack2(a45, c0, c1);
            yb[4 * T_TOT] = c0;  yb[5 * T_TOT] = c1;
            unpack2(a67, c0, c1);
            yb[6 * T_TOT] = c0;  yb[7 * T_TOT] = c1;

            __syncthreads();   // g consumed -> next tile may overwrite
        }
    }
}

extern "C" void kernel_launch(void* const* d_in, const int* in_sizes, int n_in,
                              void* d_out, int out_size)
{
    const float* u   = (const float*)d_in[0];
    const float* rlb = (const float*)d_in[1];
    const float* rom = (const float*)d_in[2];
    const float* Bc  = (const float*)d_in[3];
    const float* Cp  = (const float*)d_in[4];
    float* y = (float*)d_out;

    const int B = in_sizes[0] / (IN_CH * T_TOT);  // 8

    cudaFuncSetAttribute(ssm_rec_kernel,
                         cudaFuncAttributeMaxDynamicSharedMemorySize, SMEM_BYTES);

    dim3 grid(T_TOT / CHUNK, B);   // 64 x 8 = 512 blocks, single wave at 4/SM
    ssm_rec_kernel<<<grid, 128, SMEM_BYTES>>>(u, rlb, rom, Bc, Cp, y);
}

// round 10
// speedup vs baseline: 1.2106x; 1.2106x over previous
#include <cuda_runtime.h>
#include <math.h>

// SSMLayerFFTComplex: diagonal complex SSM (conjugate pairs) via exact linear
// recurrence instead of FFT convolution.
//
//   lam = -softplus(raw_lambda) + i*raw_omega          (per pair p)
//   A_d = exp(lam), factor = (A_d-1)/lam  (ZOH, DT=1)
//   w[b,p,t] = sum_i B_c[i,p] * u[b,i,t]               (real)
//   x[t]     = A_d * x[t-1] + factor * w[t]            (complex scan)
//   y[b,o,t] = sum_p C[p,o] * 2*Re(x[b,p,t])           (real GEMM)
//
// R9 post-mortem: two-pass stage C doubled C traffic -> regression. R10:
// keep the R8 single-pass skeleton exactly, but read C via coalesced L1-hit
// LDG.128 (each warp's per-pair C reads tile one 128B row; C is 16KB,
// read-only, shared by all blocks -> one hot L1 copy). smem drops to
// u+g = 46KB -> 4 blocks/SM, all 512 blocks in ONE wave (no tail).

namespace {
constexpr int T_TOT  = 4096;
constexpr int IN_CH  = 32;
constexpr int OUT_CH = 32;
constexpr int NP     = 128;
constexpr int CHUNK  = 64;    // useful timesteps per block
constexpr int WARM   = 32;    // warm-up timesteps
constexpr int LW     = CHUNK + WARM;   // 96
constexpr int US     = 96;             // u_s row stride
constexpr int GST    = 66;             // g row stride (b64-aligned, 2-way STS conflict only)

constexpr int U_FL = IN_CH * US;       // 3072
constexpr int G_FL = NP * GST;         // 8448
constexpr int SMEM_FLOATS = U_FL + G_FL;               // 11520
constexpr int SMEM_BYTES  = SMEM_FLOATS * (int)sizeof(float);  // 46,080 B
}

typedef unsigned long long u64;

__device__ __forceinline__ u64 ffma2(u64 a, u64 b, u64 c) {
    u64 d;
    asm("fma.rn.f32x2 %0, %1, %2, %3;" : "=l"(d) : "l"(a), "l"(b), "l"(c));
    return d;
}
__device__ __forceinline__ u64 pack2(float lo, float hi) {
    u64 d;
    asm("mov.b64 %0, {%1, %2};" : "=l"(d) : "f"(lo), "f"(hi));
    return d;
}
__device__ __forceinline__ void unpack2(u64 v, float& lo, float& hi) {
    asm("mov.b64 {%0, %1}, %2;" : "=f"(lo), "=f"(hi) : "l"(v));
}

__global__ __launch_bounds__(128, 4)
void ssm_rec_kernel(const float* __restrict__ u,
                    const float* __restrict__ raw_lambda,
                    const float* __restrict__ raw_omega,
                    const float* __restrict__ Bc,   // [IN_CH][NP]
                    const float* __restrict__ Cp,   // [NP][OUT_CH]
                    float* __restrict__ y)          // [B][OUT_CH][T]
{
    extern __shared__ float smem[];
    float* u_s = smem;              // [IN_CH][US]
    float* g_s = u_s + U_FL;        // [NP][GST]  (full 64-t chunk)

    const int tid   = threadIdx.x;
    const int wp    = tid >> 5;
    const int lane  = tid & 31;
    const int chunk = blockIdx.x;
    const int b     = blockIdx.y;
    const int t0    = chunk * CHUNK;

    const float* ug = u + (size_t)b * IN_CH * T_TOT;

    // ---- stage 0: stage u chunk (+warm-up; zero before t=0) ----
    for (int idx = tid; idx < IN_CH * LW; idx += 128) {
        int i  = idx / LW;
        int j  = idx - i * LW;
        int gt = t0 - WARM + j;
        u_s[i * US + j] = (gt >= 0) ? ug[i * T_TOT + gt] : 0.0f;
    }

    // ---- per-pair parameters (thread = pair p) ----
    const int p = tid;
    float rl = raw_lambda[p];
    float li = raw_omega[p];
    float lr = -log1pf(expf(rl));            // -softplus
    float er = expf(lr);
    float ar = er * cosf(li);                // A_d
    float ai = er * sinf(li);
    float nr = ar - 1.0f, ni = ai;
    float den = lr * lr + li * li;
    float fr, fi;
    if (den > 1e-12f) {
        float inv = 1.0f / den;
        fr = (nr * lr + ni * li) * inv;      // (A_d-1)/lam
        fi = (ni * lr - nr * li) * inv;
    } else {
        fr = 1.0f; fi = 0.0f;                // DT = 1
    }
    fr *= 2.0f; fi *= 2.0f;                  // fold 2*Re(conjugate pair)

    float bc[IN_CH];
#pragma unroll
    for (int i = 0; i < IN_CH; ++i) bc[i] = Bc[i * NP + p];

    __syncthreads();

    // ---- stage A+B: packed input mix + scan, 8 timesteps per group ----
    float xr = 0.0f, xi = 0.0f;
#pragma unroll 1
    for (int jb = 0; jb < LW; jb += 8) {
        u64 w01 = 0ull, w23 = 0ull, w45 = 0ull, w67 = 0ull;
#pragma unroll
        for (int i = 0; i < IN_CH; ++i) {
            ulonglong2 ua = *reinterpret_cast<const ulonglong2*>(&u_s[i * US + jb]);
            ulonglong2 ub = *reinterpret_cast<const ulonglong2*>(&u_s[i * US + jb + 4]);
            u64 bb = pack2(bc[i], bc[i]);
            w01 = ffma2(bb, ua.x, w01);
            w23 = ffma2(bb, ua.y, w23);
            w45 = ffma2(bb, ub.x, w45);
            w67 = ffma2(bb, ub.y, w67);
        }
        float wv[8];
        unpack2(w01, wv[0], wv[1]);
        unpack2(w23, wv[2], wv[3]);
        unpack2(w45, wv[4], wv[5]);
        unpack2(w67, wv[6], wv[7]);

        float xrs[8];
#pragma unroll
        for (int k = 0; k < 8; ++k) {
            float nxr = fmaf(ar, xr, fmaf(-ai, xi, fr * wv[k]));
            float nxi = fmaf(ar, xi, fmaf( ai, xr, fi * wv[k]));
            xr = nxr; xi = nxi;
            xrs[k] = xr;                      // already x2 via factor
        }
        if (jb >= WARM) {
            float* gr = &g_s[p * GST + (jb - WARM)];
            *reinterpret_cast<u64*>(gr + 0) = pack2(xrs[0], xrs[1]);
            *reinterpret_cast<u64*>(gr + 2) = pack2(xrs[2], xrs[3]);
            *reinterpret_cast<u64*>(gr + 4) = pack2(xrs[4], xrs[5]);
            *reinterpret_cast<u64*>(gr + 6) = pack2(xrs[6], xrs[7]);
        }
    }

    __syncthreads();

    // ---- stage C: y[o, t] = sum_p C[p,o] * g[p,t], thread = 8ch x 2t ----
    // C read directly from global: per pair, the warp's lanes (oct 0..3,
    // two 16B segments each) tile exactly one 128B C row -> coalesced
    // LDG.128, L1-resident (C = 16KB, shared by all blocks).
    const int oct = lane & 3;                       // channel octet
    const int tl  = wp * 16 + (lane >> 2) * 2;      // local t (even), 0..62

    u64 a01t0 = 0ull, a23t0 = 0ull, a45t0 = 0ull, a67t0 = 0ull;
    u64 a01t1 = 0ull, a23t1 = 0ull, a45t1 = 0ull, a67t1 = 0ull;

    const float* cb = Cp + oct * 8;
#pragma unroll 4
    for (int pp = 0; pp < NP; ++pp) {
        ulonglong2 cA = *reinterpret_cast<const ulonglong2*>(cb + pp * OUT_CH);
        ulonglong2 cB = *reinterpret_cast<const ulonglong2*>(cb + pp * OUT_CH + 4);
        u64 gp = *reinterpret_cast<const u64*>(&g_s[pp * GST + tl]);
        float g0, g1;
        unpack2(gp, g0, g1);
        u64 gg0 = pack2(g0, g0);
        u64 gg1 = pack2(g1, g1);
        a01t0 = ffma2(cA.x, gg0, a01t0);
        a23t0 = ffma2(cA.y, gg0, a23t0);
        a45t0 = ffma2(cB.x, gg0, a45t0);
        a67t0 = ffma2(cB.y, gg0, a67t0);
        a01t1 = ffma2(cA.x, gg1, a01t1);
        a23t1 = ffma2(cA.y, gg1, a23t1);
        a45t1 = ffma2(cB.x, gg1, a45t1);
        a67t1 = ffma2(cB.y, gg1, a67t1);
    }

    // ---- stores: per channel, float2 over the t-pair ----
    const int tg = t0 + tl;
    float* yb = y + ((size_t)b * OUT_CH + oct * 8) * T_TOT + tg;
    float c0t0, c1t0, c0t1, c1t1;
    unpack2(a01t0, c0t0, c1t0); unpack2(a01t1, c0t1, c1t1);
    *reinterpret_cast<float2*>(yb + 0 * T_TOT) = make_float2(c0t0, c0t1);
    *reinterpret_cast<float2*>(yb + 1 * T_TOT) = make_float2(c1t0, c1t1);
    unpack2(a23t0, c0t0, c1t0); unpack2(a23t1, c0t1, c1t1);
    *reinterpret_cast<float2*>(yb + 2 * T_TOT) = make_float2(c0t0, c0t1);
    *reinterpret_cast<float2*>(yb + 3 * T_TOT) = make_float2(c1t0, c1t1);
    unpack2(a45t0, c0t0, c1t0); unpack2(a45t1, c0t1, c1t1);
    *reinterpret_cast<float2*>(yb + 4 * T_TOT) = make_float2(c0t0, c0t1);
    *reinterpret_cast<float2*>(yb + 5 * T_TOT) = make_float2(c1t0, c1t1);
    unpack2(a67t0, c0t0, c1t0); unpack2(a67t1, c0t1, c1t1);
    *reinterpret_cast<float2*>(yb + 6 * T_TOT) = make_float2(c0t0, c0t1);
    *reinterpret_cast<float2*>(yb + 7 * T_TOT) = make_float2(c1t0, c1t1);
}

extern "C" void kernel_launch(void* const* d_in, const int* in_sizes, int n_in,
                              void* d_out, int out_size)
{
    const float* u   = (const float*)d_in[0];
    const float* rlb = (const float*)d_in[1];
    const float* rom = (const float*)d_in[2];
    const float* Bc  = (const float*)d_in[3];
    const float* Cp  = (const float*)d_in[4];
    float* y = (float*)d_out;

    const int B = in_sizes[0] / (IN_CH * T_TOT);  // 8

    cudaFuncSetAttribute(ssm_rec_kernel,
                         cudaFuncAttributeMaxDynamicSharedMemorySize, SMEM_BYTES);

    dim3 grid(T_TOT / CHUNK, B);   // 64 x 8 = 512 blocks, single wave at 4/SM
    ssm_rec_kernel<<<grid, 128, SMEM_BYTES>>>(u, rlb, rom, Bc, Cp, y);
}

// round 11
// speedup vs baseline: 1.2362x; 1.0211x over previous
#include <cuda_runtime.h>
#include <math.h>

// SSMLayerFFTComplex: diagonal complex SSM (conjugate pairs) via exact linear
// recurrence instead of FFT convolution.
//
//   lam = -softplus(raw_lambda) + i*raw_omega          (per pair p)
//   A_d = exp(lam), factor = (A_d-1)/lam  (ZOH, DT=1)
//   w[b,p,t] = sum_i B_c[i,p] * u[b,i,t]               (real)
//   x[t]     = A_d * x[t-1] + factor * w[t]            (complex scan)
//   y[b,o,t] = sum_p C[p,o] * 2*Re(x[b,p,t])           (real GEMM)
//
// R10 post-mortem: fused stage A is 48% of instructions with 32x broadcast
// amplification + 1.5x warm redundancy. R11: two kernels.
//   K1: w = Bc^T u as a register-tiled GEMM (8p x 8t per thread), written
//       once for ALL t to an L2-resident scratch w[b][t][p] (16.8MB).
//   K2: scan + stage C (R10 structure); reads its 96-t w window via
//       coalesced LDG.32 (warm-up = re-READ, not re-compute), g in smem,
//       C via L1-hot LDG.128. ~2500 instr/warp vs ~5000 fused.

namespace {
constexpr int T_TOT  = 4096;
constexpr int IN_CH  = 32;
constexpr int OUT_CH = 32;
constexpr int NP     = 128;
constexpr int CHUNK  = 64;    // useful timesteps per block (both kernels)
constexpr int WARM   = 32;    // warm-up timesteps (K2)
constexpr int LW     = CHUNK + WARM;   // 96
constexpr int GST    = 66;             // g row stride (b64-aligned, 2-way STS only)
constexpr int G_FL   = NP * GST;       // 8448
constexpr int SMEM2_BYTES = G_FL * (int)sizeof(float);  // 33,792 B

// K1 tile: block = 128 threads computes [CHUNK t][NP p]; thread = 8p x 8t.
constexpr int K1_U_FL  = IN_CH * CHUNK;   // 2048
constexpr int K1_BC_FL = IN_CH * NP;      // 4096
constexpr int SMEM1_BYTES = (K1_U_FL + K1_BC_FL) * (int)sizeof(float);  // 24,576 B
constexpr int MAXB = 8;
}

__device__ float w_buf[MAXB * T_TOT * NP];   // scratch: w[b][t][p]

typedef unsigned long long u64;

__device__ __forceinline__ u64 ffma2(u64 a, u64 b, u64 c) {
    u64 d;
    asm("fma.rn.f32x2 %0, %1, %2, %3;" : "=l"(d) : "l"(a), "l"(b), "l"(c));
    return d;
}
__device__ __forceinline__ u64 pack2(float lo, float hi) {
    u64 d;
    asm("mov.b64 %0, {%1, %2};" : "=l"(d) : "f"(lo), "f"(hi));
    return d;
}
__device__ __forceinline__ void unpack2(u64 v, float& lo, float& hi) {
    asm("mov.b64 {%0, %1}, %2;" : "=f"(lo), "=f"(hi) : "l"(v));
}

// ---------------------------------------------------------------------------
// Kernel 1: w[b][t][p] = sum_i Bc[i][p] * u[b][i][t]
// ---------------------------------------------------------------------------
__global__ __launch_bounds__(128, 4)
void ssm_wmix_kernel(const float* __restrict__ u,
                     const float* __restrict__ Bc)
{
    extern __shared__ float smem[];
    float* u_s  = smem;                 // [IN_CH][CHUNK]
    float* bc_s = smem + K1_U_FL;       // [IN_CH][NP]

    const int tid = threadIdx.x;
    const int ct  = blockIdx.x;
    const int b   = blockIdx.y;
    const int t0  = ct * CHUNK;

    // stage u tile (rows of 64 consecutive t -> coalesced)
    const float* ug = u + (size_t)b * IN_CH * T_TOT + t0;
    for (int idx = tid; idx < K1_U_FL; idx += 128) {
        int i = idx >> 6;           // / CHUNK
        int j = idx & 63;
        u_s[idx] = ug[i * T_TOT + j];
    }
    for (int idx = tid; idx < K1_BC_FL; idx += 128) bc_s[idx] = Bc[idx];
    __syncthreads();

    const int pq = tid & 15;        // p block: [8*pq, 8*pq+8)
    const int tq = tid >> 4;        // t block: [8*tq, 8*tq+8)

    u64 acc[8][4];                  // [t][p-pair]
#pragma unroll
    for (int t = 0; t < 8; ++t)
#pragma unroll
        for (int q = 0; q < 4; ++q) acc[t][q] = 0ull;

    const float* bcb = bc_s + 8 * pq;
    const float* ub  = u_s + 8 * tq;
#pragma unroll 4
    for (int k = 0; k < IN_CH; ++k) {
        ulonglong2 bcp = *reinterpret_cast<const ulonglong2*>(bcb + k * NP);
        ulonglong2 bcq = *reinterpret_cast<const ulonglong2*>(bcb + k * NP + 4);
        float4 ua = *reinterpret_cast<const float4*>(ub + k * CHUNK);
        float4 ub4 = *reinterpret_cast<const float4*>(ub + k * CHUNK + 4);
        u64 td[8];
        td[0] = pack2(ua.x, ua.x);  td[1] = pack2(ua.y, ua.y);
        td[2] = pack2(ua.z, ua.z);  td[3] = pack2(ua.w, ua.w);
        td[4] = pack2(ub4.x, ub4.x); td[5] = pack2(ub4.y, ub4.y);
        td[6] = pack2(ub4.z, ub4.z); td[7] = pack2(ub4.w, ub4.w);
        u64 bp[4] = {bcp.x, bcp.y, bcq.x, bcq.y};
#pragma unroll
        for (int t = 0; t < 8; ++t)
#pragma unroll
            for (int q = 0; q < 4; ++q)
                acc[t][q] = ffma2(bp[q], td[t], acc[t][q]);
    }

    // store: w[b][t0+8tq+t][8pq .. 8pq+8)
    float* wb = w_buf + ((size_t)b * T_TOT + t0 + 8 * tq) * NP + 8 * pq;
#pragma unroll
    for (int t = 0; t < 8; ++t) {
        ulonglong2 v0; v0.x = acc[t][0]; v0.y = acc[t][1];
        ulonglong2 v1; v1.x = acc[t][2]; v1.y = acc[t][3];
        *reinterpret_cast<ulonglong2*>(wb + t * NP)     = v0;
        *reinterpret_cast<ulonglong2*>(wb + t * NP + 4) = v1;
    }
}

// ---------------------------------------------------------------------------
// Kernel 2: scan + output GEMM
// ---------------------------------------------------------------------------
__global__ __launch_bounds__(128, 4)
void ssm_scan_kernel(const float* __restrict__ raw_lambda,
                     const float* __restrict__ raw_omega,
                     const float* __restrict__ Cp,   // [NP][OUT_CH]
                     float* __restrict__ y)          // [B][OUT_CH][T]
{
    extern __shared__ float smem[];
    float* g_s = smem;              // [NP][GST]  (full 64-t chunk)

    const int tid   = threadIdx.x;
    const int wp    = tid >> 5;
    const int lane  = tid & 31;
    const int chunk = blockIdx.x;
    const int b     = blockIdx.y;
    const int t0    = chunk * CHUNK;

    // ---- per-pair parameters (thread = pair p) ----
    const int p = tid;
    float rl = raw_lambda[p];
    float li = raw_omega[p];
    float lr = -log1pf(expf(rl));            // -softplus
    float er = expf(lr);
    float ar = er * cosf(li);                // A_d
    float ai = er * sinf(li);
    float nr = ar - 1.0f, ni = ai;
    float den = lr * lr + li * li;
    float fr, fi;
    if (den > 1e-12f) {
        float inv = 1.0f / den;
        fr = (nr * lr + ni * li) * inv;      // (A_d-1)/lam
        fi = (ni * lr - nr * li) * inv;
    } else {
        fr = 1.0f; fi = 0.0f;                // DT = 1
    }
    fr *= 2.0f; fi *= 2.0f;                  // fold 2*Re(conjugate pair)

    // ---- stage B: scan over [t0-WARM, t0+CHUNK), w from L2 scratch ----
    const float* wrow = w_buf + (size_t)b * T_TOT * NP + p;
    float xr = 0.0f, xi = 0.0f;
#pragma unroll 1
    for (int jb = 0; jb < LW; jb += 8) {
        const int tb = t0 - WARM + jb;
        float wv[8];
        if (tb >= 0) {                       // uniform per block
#pragma unroll
            for (int k = 0; k < 8; ++k) wv[k] = wrow[(size_t)(tb + k) * NP];
        } else {                             // WARM%8==0 -> whole group < 0
#pragma unroll
            for (int k = 0; k < 8; ++k) wv[k] = 0.0f;
        }

        float xrs[8];
#pragma unroll
        for (int k = 0; k < 8; ++k) {
            float nxr = fmaf(ar, xr, fmaf(-ai, xi, fr * wv[k]));
            float nxi = fmaf(ar, xi, fmaf( ai, xr, fi * wv[k]));
            xr = nxr; xi = nxi;
            xrs[k] = xr;                      // already x2 via factor
        }
        if (jb >= WARM) {
            float* gr = &g_s[p * GST + (jb - WARM)];
            *reinterpret_cast<u64*>(gr + 0) = pack2(xrs[0], xrs[1]);
            *reinterpret_cast<u64*>(gr + 2) = pack2(xrs[2], xrs[3]);
            *reinterpret_cast<u64*>(gr + 4) = pack2(xrs[4], xrs[5]);
            *reinterpret_cast<u64*>(gr + 6) = pack2(xrs[6], xrs[7]);
        }
    }

    __syncthreads();

    // ---- stage C: y[o, t] = sum_p C[p,o] * g[p,t], thread = 8ch x 2t ----
    // C read via coalesced LDG.128 (16KB, shared by all blocks, L1-hot).
    const int oct = lane & 3;                       // channel octet
    const int tl  = wp * 16 + (lane >> 2) * 2;      // local t (even), 0..62

    u64 a01t0 = 0ull, a23t0 = 0ull, a45t0 = 0ull, a67t0 = 0ull;
    u64 a01t1 = 0ull, a23t1 = 0ull, a45t1 = 0ull, a67t1 = 0ull;

    const float* cb = Cp + oct * 8;
#pragma unroll 4
    for (int pp = 0; pp < NP; ++pp) {
        ulonglong2 cA = *reinterpret_cast<const ulonglong2*>(cb + pp * OUT_CH);
        ulonglong2 cB = *reinterpret_cast<const ulonglong2*>(cb + pp * OUT_CH + 4);
        u64 gp = *reinterpret_cast<const u64*>(&g_s[pp * GST + tl]);
        float g0, g1;
        unpack2(gp, g0, g1);
        u64 gg0 = pack2(g0, g0);
        u64 gg1 = pack2(g1, g1);
        a01t0 = ffma2(cA.x, gg0, a01t0);
        a23t0 = ffma2(cA.y, gg0, a23t0);
        a45t0 = ffma2(cB.x, gg0, a45t0);
        a67t0 = ffma2(cB.y, gg0, a67t0);
        a01t1 = ffma2(cA.x, gg1, a01t1);
        a23t1 = ffma2(cA.y, gg1, a23t1);
        a45t1 = ffma2(cB.x, gg1, a45t1);
        a67t1 = ffma2(cB.y, gg1, a67t1);
    }

    const int tg = t0 + tl;
    float* yb = y + ((size_t)b * OUT_CH + oct * 8) * T_TOT + tg;
    float c0t0, c1t0, c0t1, c1t1;
    unpack2(a01t0, c0t0, c1t0); unpack2(a01t1, c0t1, c1t1);
    *reinterpret_cast<float2*>(yb + 0 * T_TOT) = make_float2(c0t0, c0t1);
    *reinterpret_cast<float2*>(yb + 1 * T_TOT) = make_float2(c1t0, c1t1);
    unpack2(a23t0, c0t0, c1t0); unpack2(a23t1, c0t1, c1t1);
    *reinterpret_cast<float2*>(yb + 2 * T_TOT) = make_float2(c0t0, c0t1);
    *reinterpret_cast<float2*>(yb + 3 * T_TOT) = make_float2(c1t0, c1t1);
    unpack2(a45t0, c0t0, c1t0); unpack2(a45t1, c0t1, c1t1);
    *reinterpret_cast<float2*>(yb + 4 * T_TOT) = make_float2(c0t0, c0t1);
    *reinterpret_cast<float2*>(yb + 5 * T_TOT) = make_float2(c1t0, c1t1);
    unpack2(a67t0, c0t0, c1t0); unpack2(a67t1, c0t1, c1t1);
    *reinterpret_cast<float2*>(yb + 6 * T_TOT) = make_float2(c0t0, c0t1);
    *reinterpret_cast<float2*>(yb + 7 * T_TOT) = make_float2(c1t0, c1t1);
}

extern "C" void kernel_launch(void* const* d_in, const int* in_sizes, int n_in,
                              void* d_out, int out_size)
{
    const float* u   = (const float*)d_in[0];
    const float* rlb = (const float*)d_in[1];
    const float* rom = (const float*)d_in[2];
    const float* Bc  = (const float*)d_in[3];
    const float* Cp  = (const float*)d_in[4];
    float* y = (float*)d_out;

    const int B = in_sizes[0] / (IN_CH * T_TOT);  // 8

    cudaFuncSetAttribute(ssm_wmix_kernel,
                         cudaFuncAttributeMaxDynamicSharedMemorySize, SMEM1_BYTES);
    cudaFuncSetAttribute(ssm_scan_kernel,
                         cudaFuncAttributeMaxDynamicSharedMemorySize, SMEM2_BYTES);

    dim3 grid(T_TOT / CHUNK, B);   // 64 x 8 = 512 blocks each
    ssm_wmix_kernel<<<grid, 128, SMEM1_BYTES>>>(u, Bc);
    ssm_scan_kernel<<<grid, 128, SMEM2_BYTES>>>(rlb, rom, Cp, y);
}